// round 1
// baseline (speedup 1.0000x reference)
#include <cuda_runtime.h>
#include <math.h>

// ---------------------------------------------------------------------------
// Problem constants
// ---------------------------------------------------------------------------
#define B_    2
#define T_    1024
#define D_    768
#define H_    12
#define L_    4
#define E_    8
#define DFF_  3072
#define V_    32000
#define HEAD_ 64
#define BT_   (B_ * T_)

// ---------------------------------------------------------------------------
// Scratch (device globals: allocation-free rule)
// ---------------------------------------------------------------------------
__device__ float g_x[BT_ * D_];
__device__ float g_h[BT_ * D_];
__device__ float g_qkv[BT_ * 3 * D_];
__device__ float g_scores[(size_t)B_ * H_ * T_ * T_];
__device__ float g_attnout[BT_ * D_];
__device__ float g_hid[(size_t)E_ * BT_ * DFF_];
__device__ float g_eo[(size_t)E_ * BT_ * D_];
__device__ float g_mp[BT_ * E_];

// ---------------------------------------------------------------------------
// Block reductions (blockDim.x == 256)
// ---------------------------------------------------------------------------
__device__ __forceinline__ void block_reduce_sum2(float& a, float& b) {
    __shared__ float sa[8], sb[8];
#pragma unroll
    for (int o = 16; o > 0; o >>= 1) {
        a += __shfl_xor_sync(0xffffffffu, a, o);
        b += __shfl_xor_sync(0xffffffffu, b, o);
    }
    int w = threadIdx.x >> 5;
    if ((threadIdx.x & 31) == 0) { sa[w] = a; sb[w] = b; }
    __syncthreads();
    if (threadIdx.x < 32) {
        float x = (threadIdx.x < 8) ? sa[threadIdx.x] : 0.f;
        float y = (threadIdx.x < 8) ? sb[threadIdx.x] : 0.f;
#pragma unroll
        for (int o = 4; o > 0; o >>= 1) {
            x += __shfl_xor_sync(0xffffffffu, x, o);
            y += __shfl_xor_sync(0xffffffffu, y, o);
        }
        if (threadIdx.x == 0) { sa[0] = x; sb[0] = y; }
    }
    __syncthreads();
    float ra = sa[0], rb = sb[0];
    __syncthreads();
    a = ra; b = rb;
}

__device__ __forceinline__ float block_reduce_max(float a) {
    __shared__ float sm[8];
#pragma unroll
    for (int o = 16; o > 0; o >>= 1) a = fmaxf(a, __shfl_xor_sync(0xffffffffu, a, o));
    int w = threadIdx.x >> 5;
    if ((threadIdx.x & 31) == 0) sm[w] = a;
    __syncthreads();
    if (threadIdx.x < 32) {
        float x = (threadIdx.x < 8) ? sm[threadIdx.x] : -1e30f;
#pragma unroll
        for (int o = 4; o > 0; o >>= 1) x = fmaxf(x, __shfl_xor_sync(0xffffffffu, x, o));
        if (threadIdx.x == 0) sm[0] = x;
    }
    __syncthreads();
    float r = sm[0];
    __syncthreads();
    return r;
}

__device__ __forceinline__ float block_reduce_sum(float a) {
    __shared__ float ss[8];
#pragma unroll
    for (int o = 16; o > 0; o >>= 1) a += __shfl_xor_sync(0xffffffffu, a, o);
    int w = threadIdx.x >> 5;
    if ((threadIdx.x & 31) == 0) ss[w] = a;
    __syncthreads();
    if (threadIdx.x < 32) {
        float x = (threadIdx.x < 8) ? ss[threadIdx.x] : 0.f;
#pragma unroll
        for (int o = 4; o > 0; o >>= 1) x += __shfl_xor_sync(0xffffffffu, x, o);
        if (threadIdx.x == 0) ss[0] = x;
    }
    __syncthreads();
    float r = ss[0];
    __syncthreads();
    return r;
}

// ---------------------------------------------------------------------------
// Embedding gather + LayerNorm (fused).  One block per token, 256 threads.
// ---------------------------------------------------------------------------
__global__ __launch_bounds__(256) void embed_ln_kernel(
    const int* __restrict__ tokens, const float* __restrict__ wte,
    const float* __restrict__ wpe, const float* __restrict__ g,
    const float* __restrict__ b, float* __restrict__ out)
{
    int row = blockIdx.x;
    int t   = row & (T_ - 1);
    int tok = tokens[row];
    const float* we = wte + (size_t)tok * D_;
    const float* pe = wpe + (size_t)t * D_;
    float v[3], s = 0.f, ss = 0.f;
#pragma unroll
    for (int i = 0; i < 3; i++) {
        int idx = threadIdx.x + i * 256;
        float x = we[idx] + pe[idx];
        v[i] = x; s += x; ss += x * x;
    }
    block_reduce_sum2(s, ss);
    float mean = s * (1.f / D_);
    float var  = ss * (1.f / D_) - mean * mean;
    float rstd = rsqrtf(var + 1e-5f);
#pragma unroll
    for (int i = 0; i < 3; i++) {
        int idx = threadIdx.x + i * 256;
        out[(size_t)row * D_ + idx] = (v[i] - mean) * rstd * g[idx] + b[idx];
    }
}

// ---------------------------------------------------------------------------
// Generic LayerNorm.  One block per row.
// ---------------------------------------------------------------------------
__global__ __launch_bounds__(256) void ln_kernel(
    const float* __restrict__ in, const float* __restrict__ g,
    const float* __restrict__ b, float* __restrict__ out)
{
    int row = blockIdx.x;
    const float* ir = in + (size_t)row * D_;
    float v[3], s = 0.f, ss = 0.f;
#pragma unroll
    for (int i = 0; i < 3; i++) {
        int idx = threadIdx.x + i * 256;
        float x = ir[idx];
        v[i] = x; s += x; ss += x * x;
    }
    block_reduce_sum2(s, ss);
    float mean = s * (1.f / D_);
    float var  = ss * (1.f / D_) - mean * mean;
    float rstd = rsqrtf(var + 1e-5f);
#pragma unroll
    for (int i = 0; i < 3; i++) {
        int idx = threadIdx.x + i * 256;
        out[(size_t)row * D_ + idx] = (v[i] - mean) * rstd * g[idx] + b[idx];
    }
}

// ---------------------------------------------------------------------------
// Batched SGEMM (NT):  C[z] = A[z] (MxK, row-major) * B[z] (NxK, row-major)^T
// BM=BN=128, BK=8, 256 threads, 8x8 per thread. All dims divide exactly.
// EPI: 0 = store, 1 = relu+store, 2 = add into C.
// ---------------------------------------------------------------------------
template <int EPI>
__global__ __launch_bounds__(256) void sgemm_nt_kernel(
    const float* __restrict__ A, const float* __restrict__ B,
    float* __restrict__ C, int K, int N,
    size_t sA, size_t sB, size_t sC)
{
    A += (size_t)blockIdx.z * sA;
    B += (size_t)blockIdx.z * sB;
    C += (size_t)blockIdx.z * sC;

    __shared__ float As[8][128];
    __shared__ float Bs[8][128];

    const int tid  = threadIdx.x;
    const int lrow = tid >> 1;          // 0..127
    const int lcol = (tid & 1) << 2;    // 0 or 4
    const float* Ap = A + (size_t)(blockIdx.y * 128 + lrow) * K + lcol;
    const float* Bp = B + (size_t)(blockIdx.x * 128 + lrow) * K + lcol;

    const int tx = (tid & 15) << 3;     // col offset in tile
    const int ty = (tid >> 4) << 3;     // row offset in tile

    float acc[8][8];
#pragma unroll
    for (int i = 0; i < 8; i++)
#pragma unroll
        for (int j = 0; j < 8; j++) acc[i][j] = 0.f;

    for (int k0 = 0; k0 < K; k0 += 8) {
        float4 a4 = *(const float4*)(Ap + k0);
        float4 b4 = *(const float4*)(Bp + k0);
        As[lcol + 0][lrow] = a4.x; As[lcol + 1][lrow] = a4.y;
        As[lcol + 2][lrow] = a4.z; As[lcol + 3][lrow] = a4.w;
        Bs[lcol + 0][lrow] = b4.x; Bs[lcol + 1][lrow] = b4.y;
        Bs[lcol + 2][lrow] = b4.z; Bs[lcol + 3][lrow] = b4.w;
        __syncthreads();
#pragma unroll
        for (int kk = 0; kk < 8; kk++) {
            float4 a0 = *(const float4*)&As[kk][ty];
            float4 a1 = *(const float4*)&As[kk][ty + 4];
            float4 b0 = *(const float4*)&Bs[kk][tx];
            float4 b1 = *(const float4*)&Bs[kk][tx + 4];
            float av[8] = {a0.x, a0.y, a0.z, a0.w, a1.x, a1.y, a1.z, a1.w};
            float bv[8] = {b0.x, b0.y, b0.z, b0.w, b1.x, b1.y, b1.z, b1.w};
#pragma unroll
            for (int i = 0; i < 8; i++)
#pragma unroll
                for (int j = 0; j < 8; j++)
                    acc[i][j] = fmaf(av[i], bv[j], acc[i][j]);
        }
        __syncthreads();
    }

    const int row0 = blockIdx.y * 128 + ty;
    const int col0 = blockIdx.x * 128 + tx;
#pragma unroll
    for (int i = 0; i < 8; i++) {
        float* cp = C + (size_t)(row0 + i) * N + col0;
#pragma unroll
        for (int jj = 0; jj < 2; jj++) {
            float4 v = make_float4(acc[i][jj * 4 + 0], acc[i][jj * 4 + 1],
                                   acc[i][jj * 4 + 2], acc[i][jj * 4 + 3]);
            if (EPI == 1) {
                v.x = fmaxf(v.x, 0.f); v.y = fmaxf(v.y, 0.f);
                v.z = fmaxf(v.z, 0.f); v.w = fmaxf(v.w, 0.f);
            }
            if (EPI == 2) {
                float4 o = *(const float4*)(cp + jj * 4);
                v.x += o.x; v.y += o.y; v.z += o.z; v.w += o.w;
            }
            *(float4*)(cp + jj * 4) = v;
        }
    }
}

// ---------------------------------------------------------------------------
// Attention scores: scores[bh,q,k] = (q·k) / 8 for a 64x64 tile.
// Blocks fully above the diagonal are skipped (never read downstream).
// ---------------------------------------------------------------------------
__global__ __launch_bounds__(256) void attn_scores_kernel(
    const float* __restrict__ qkv, float* __restrict__ scores)
{
    const int bh = blockIdx.z, b = bh / H_, h = bh % H_;
    const int qb = blockIdx.y, kb = blockIdx.x;
    if (kb > qb) return;   // fully masked tile

    __shared__ float Qs[64][65];
    __shared__ float Ks[64][65];

    const int tid = threadIdx.x;
    {
        int row = tid >> 2;            // 0..63
        int c0  = (tid & 3) * 16;      // 0,16,32,48
        const float* qptr = qkv + ((size_t)(b * T_ + qb * 64 + row)) * (3 * D_) + h * 64 + c0;
        const float* kptr = qkv + ((size_t)(b * T_ + kb * 64 + row)) * (3 * D_) + D_ + h * 64 + c0;
#pragma unroll
        for (int i = 0; i < 16; i += 4) {
            float4 q4 = *(const float4*)(qptr + i);
            Qs[row][c0 + i + 0] = q4.x; Qs[row][c0 + i + 1] = q4.y;
            Qs[row][c0 + i + 2] = q4.z; Qs[row][c0 + i + 3] = q4.w;
            float4 k4 = *(const float4*)(kptr + i);
            Ks[row][c0 + i + 0] = k4.x; Ks[row][c0 + i + 1] = k4.y;
            Ks[row][c0 + i + 2] = k4.z; Ks[row][c0 + i + 3] = k4.w;
        }
    }
    __syncthreads();

    const int tx = tid & 15, ty = tid >> 4;
    float acc[4][4];
#pragma unroll
    for (int i = 0; i < 4; i++)
#pragma unroll
        for (int j = 0; j < 4; j++) acc[i][j] = 0.f;

#pragma unroll 4
    for (int j = 0; j < 64; j++) {
        float av[4], bv[4];
#pragma unroll
        for (int i = 0; i < 4; i++) av[i] = Qs[ty * 4 + i][j];
#pragma unroll
        for (int i = 0; i < 4; i++) bv[i] = Ks[tx * 4 + i][j];
#pragma unroll
        for (int i = 0; i < 4; i++)
#pragma unroll
            for (int jj = 0; jj < 4; jj++)
                acc[i][jj] = fmaf(av[i], bv[jj], acc[i][jj]);
    }

    float* sp = scores + (size_t)bh * T_ * T_;
#pragma unroll
    for (int i = 0; i < 4; i++) {
        size_t off = (size_t)(qb * 64 + ty * 4 + i) * T_ + kb * 64 + tx * 4;
        float4 v = make_float4(acc[i][0] * 0.125f, acc[i][1] * 0.125f,
                               acc[i][2] * 0.125f, acc[i][3] * 0.125f);
        *(float4*)(sp + off) = v;
    }
}

// ---------------------------------------------------------------------------
// Causal softmax in-place over scores rows; zeros the masked tail.
// One block per (bh, q) row.
// ---------------------------------------------------------------------------
__global__ __launch_bounds__(256) void softmax_kernel(float* __restrict__ p)
{
    size_t r = blockIdx.x;
    int q = (int)(r & (T_ - 1));
    float* row = p + r * (size_t)T_;

    float m = -1e30f;
    for (int k = threadIdx.x; k <= q; k += 256) m = fmaxf(m, row[k]);
    m = block_reduce_max(m);

    float s = 0.f;
    for (int k = threadIdx.x; k <= q; k += 256) {
        float e = expf(row[k] - m);
        row[k] = e; s += e;
    }
    s = block_reduce_sum(s);
    float inv = 1.f / s;
    for (int k = threadIdx.x; k <= q; k += 256) row[k] *= inv;
    for (int k = q + 1 + threadIdx.x; k < T_; k += 256) row[k] = 0.f;
}

// ---------------------------------------------------------------------------
// P @ V : out[b, q, h*64 + d] = sum_k P[bh,q,k] * V[b,k,h,d]
// One block per (q-tile, bh); loops only over k-tiles <= q-tile (causal).
// ---------------------------------------------------------------------------
__global__ __launch_bounds__(256) void attn_pv_kernel(
    const float* __restrict__ p, const float* __restrict__ qkv,
    float* __restrict__ attnout)
{
    const int bh = blockIdx.y, b = bh / H_, h = bh % H_;
    const int qb = blockIdx.x;

    __shared__ float Ps[64][65];
    __shared__ float Vs[64][64];

    const int tid = threadIdx.x;
    const int tx = tid & 15, ty = tid >> 4;
    float acc[4][4];
#pragma unroll
    for (int i = 0; i < 4; i++)
#pragma unroll
        for (int j = 0; j < 4; j++) acc[i][j] = 0.f;

    const int lr = tid >> 2;           // 0..63
    const int c0 = (tid & 3) * 16;

    for (int kt = 0; kt <= qb; kt++) {
        const float* pptr = p + ((size_t)bh * T_ + qb * 64 + lr) * T_ + kt * 64 + c0;
        const float* vptr = qkv + ((size_t)(b * T_ + kt * 64 + lr)) * (3 * D_) + 2 * D_ + h * 64 + c0;
#pragma unroll
        for (int i = 0; i < 16; i += 4) {
            float4 p4 = *(const float4*)(pptr + i);
            Ps[lr][c0 + i + 0] = p4.x; Ps[lr][c0 + i + 1] = p4.y;
            Ps[lr][c0 + i + 2] = p4.z; Ps[lr][c0 + i + 3] = p4.w;
            float4 v4 = *(const float4*)(vptr + i);
            *(float4*)&Vs[lr][c0 + i] = v4;
        }
        __syncthreads();
#pragma unroll 4
        for (int kk = 0; kk < 64; kk++) {
            float av[4];
#pragma unroll
            for (int i = 0; i < 4; i++) av[i] = Ps[ty * 4 + i][kk];
            float4 b4 = *(const float4*)&Vs[kk][tx * 4];
            float bv[4] = {b4.x, b4.y, b4.z, b4.w};
#pragma unroll
            for (int i = 0; i < 4; i++)
#pragma unroll
                for (int j = 0; j < 4; j++)
                    acc[i][j] = fmaf(av[i], bv[j], acc[i][j]);
        }
        __syncthreads();
    }

#pragma unroll
    for (int i = 0; i < 4; i++) {
        size_t off = (size_t)(b * T_ + qb * 64 + ty * 4 + i) * D_ + h * 64 + tx * 4;
        *(float4*)(attnout + off) = make_float4(acc[i][0], acc[i][1], acc[i][2], acc[i][3]);
    }
}

// ---------------------------------------------------------------------------
// Router: scores, softmax over E=8, top-2 mask + renormalize -> mp[B*T, E]
// One block per token; warp w computes expert-w dot product.
// ---------------------------------------------------------------------------
__global__ __launch_bounds__(256) void router_kernel(
    const float* __restrict__ h, const float* __restrict__ rw,
    float* __restrict__ mp)
{
    int row  = blockIdx.x;
    int w    = threadIdx.x >> 5, lane = threadIdx.x & 31;
    const float* hr = h + (size_t)row * D_;
    const float* wr = rw + (size_t)w * D_;
    float s = 0.f;
    for (int j = lane; j < D_; j += 32) s = fmaf(hr[j], wr[j], s);
#pragma unroll
    for (int o = 16; o > 0; o >>= 1) s += __shfl_xor_sync(0xffffffffu, s, o);
    __shared__ float sc[E_];
    if (lane == 0) sc[w] = s;
    __syncthreads();
    if (threadIdx.x == 0) {
        float mx = sc[0];
#pragma unroll
        for (int e = 1; e < E_; e++) mx = fmaxf(mx, sc[e]);
        float pr[E_], sum = 0.f;
#pragma unroll
        for (int e = 0; e < E_; e++) { pr[e] = expf(sc[e] - mx); sum += pr[e]; }
        int i1 = 0;
#pragma unroll
        for (int e = 1; e < E_; e++) if (sc[e] > sc[i1]) i1 = e;
        int i2 = (i1 == 0) ? 1 : 0;
#pragma unroll
        for (int e = 0; e < E_; e++) if (e != i1 && sc[e] > sc[i2]) i2 = e;
        float p1 = pr[i1] / sum, p2 = pr[i2] / sum;
        float inv = 1.f / (p1 + p2 + 1e-8f);
#pragma unroll
        for (int e = 0; e < E_; e++) mp[(size_t)row * E_ + e] = 0.f;
        mp[(size_t)row * E_ + i1] = p1 * inv;
        mp[(size_t)row * E_ + i2] = p2 * inv;
    }
}

// ---------------------------------------------------------------------------
// x += sum_e mp[row,e] * eo[e, row, :]
// ---------------------------------------------------------------------------
__global__ __launch_bounds__(256) void moe_combine_kernel(
    const float* __restrict__ eo, const float* __restrict__ mp,
    float* __restrict__ x)
{
    int i   = blockIdx.x * 256 + threadIdx.x;
    int row = i / D_;
    const float* m = mp + (size_t)row * E_;
    float acc = x[i];
#pragma unroll
    for (int e = 0; e < E_; e++)
        acc = fmaf(m[e], eo[(size_t)e * ((size_t)BT_ * D_) + i], acc);
    x[i] = acc;
}

// ---------------------------------------------------------------------------
// Launch
// ---------------------------------------------------------------------------
extern "C" void kernel_launch(void* const* d_in, const int* in_sizes, int n_in,
                              void* d_out, int out_size)
{
    (void)in_sizes; (void)n_in; (void)out_size;
    const int*   tokens  = (const int*)  d_in[0];
    const float* wte     = (const float*)d_in[1];
    const float* wpe     = (const float*)d_in[2];
    const float* n0g     = (const float*)d_in[3];
    const float* n0b     = (const float*)d_in[4];
    const float* n1g     = (const float*)d_in[5];
    const float* n1b     = (const float*)d_in[6];
    const float* n2g     = (const float*)d_in[7];
    const float* n2b     = (const float*)d_in[8];
    const float* qkvw    = (const float*)d_in[9];
    const float* projw   = (const float*)d_in[10];
    const float* routerw = (const float*)d_in[11];
    const float* fc1     = (const float*)d_in[12];
    const float* fc2     = (const float*)d_in[13];
    const float* lmw     = (const float*)d_in[14];
    float* out = (float*)d_out;

    float *px, *ph, *pqkv, *pscores, *pattn, *phid, *peo, *pmp;
    cudaGetSymbolAddress((void**)&px,      g_x);
    cudaGetSymbolAddress((void**)&ph,      g_h);
    cudaGetSymbolAddress((void**)&pqkv,    g_qkv);
    cudaGetSymbolAddress((void**)&pscores, g_scores);
    cudaGetSymbolAddress((void**)&pattn,   g_attnout);
    cudaGetSymbolAddress((void**)&phid,    g_hid);
    cudaGetSymbolAddress((void**)&peo,     g_eo);
    cudaGetSymbolAddress((void**)&pmp,     g_mp);

    embed_ln_kernel<<<BT_, 256>>>(tokens, wte, wpe, n0g, n0b, px);

    for (int l = 0; l < L_; l++) {
        // --- attention block ---
        ln_kernel<<<BT_, 256>>>(px, n1g + l * D_, n1b + l * D_, ph);
        sgemm_nt_kernel<0><<<dim3(3 * D_ / 128, BT_ / 128, 1), 256>>>(
            ph, qkvw + (size_t)l * 3 * D_ * D_, pqkv, D_, 3 * D_, 0, 0, 0);
        attn_scores_kernel<<<dim3(T_ / 64, T_ / 64, B_ * H_), 256>>>(pqkv, pscores);
        softmax_kernel<<<B_ * H_ * T_, 256>>>(pscores);
        attn_pv_kernel<<<dim3(T_ / 64, B_ * H_), 256>>>(pscores, pqkv, pattn);
        sgemm_nt_kernel<2><<<dim3(D_ / 128, BT_ / 128, 1), 256>>>(
            pattn, projw + (size_t)l * D_ * D_, px, D_, D_, 0, 0, 0);

        // --- MoE block (dense over all experts, faithful to reference) ---
        ln_kernel<<<BT_, 256>>>(px, n2g + l * D_, n2b + l * D_, ph);
        router_kernel<<<BT_, 256>>>(ph, routerw + (size_t)l * E_ * D_, pmp);
        sgemm_nt_kernel<1><<<dim3(DFF_ / 128, BT_ / 128, E_), 256>>>(
            ph, fc1 + (size_t)l * E_ * DFF_ * D_, phid, D_, DFF_,
            (size_t)0, (size_t)DFF_ * D_, (size_t)BT_ * DFF_);
        sgemm_nt_kernel<0><<<dim3(D_ / 128, BT_ / 128, E_), 256>>>(
            phid, fc2 + (size_t)l * E_ * D_ * DFF_, peo, DFF_, D_,
            (size_t)BT_ * DFF_, (size_t)D_ * DFF_, (size_t)BT_ * D_);
        moe_combine_kernel<<<BT_ * D_ / 256, 256>>>(peo, pmp, px);
    }

    // --- LM head ---
    sgemm_nt_kernel<0><<<dim3(V_ / 128, BT_ / 128, 1), 256>>>(
        px, lmw, out, D_, V_, 0, 0, 0);
}